// round 5
// baseline (speedup 1.0000x reference)
#include <cuda_runtime.h>
#include <cstdint>

// Shapes (fixed): B=8, S=4096, E=512 -> M=32768, N=K=512
#define M_TOT 32768
#define N_TOT 512
#define K_TOT 512

// GEMM tiling: 512 threads, 16 warps (4x4), warp tile 64x32
#define BM 256
#define BN 128
#define BK 32
#define NTH 512
#define NCH (K_TOT / BK)   // 16

// Fragment-order smem layout (floats):
//   A: [ks 0..3][mt 0..15][lane 0..31][reg 0..3]  + 4-word pad per ks block
//   B: [ks 0..3][ntp 0..7][lane 0..31][reg 0..3]  + 4-word pad per ks block
#define A_KSB 2052                   // 16*128 + 4
#define B_KSB 1028                   // 8*128 + 4
#define A_HALF (4 * A_KSB)           // 8208
#define B_HALF (4 * B_KSB)           // 4112
#define STG_FLOATS (A_HALF + B_HALF) // 12320
#define SMEM_BYTES (2 * STG_FLOATS * 4)  // 98560

// ---------------- scratch (device globals: sanctioned no-alloc path) ----------
__device__ float g_V [(size_t)M_TOT * N_TOT];
__device__ float g_Vc[(size_t)M_TOT * N_TOT];

__device__ __forceinline__ uint32_t f2tf(float x) {
    uint32_t u;
    asm("cvt.rna.tf32.f32 %0, %1;" : "=r"(u) : "f"(x));
    return u;
}

__device__ __forceinline__ void mma8(float* c, const uint32_t* a,
                                     uint32_t b0, uint32_t b1) {
    asm volatile(
        "mma.sync.aligned.m16n8k8.row.col.f32.tf32.tf32.f32 "
        "{%0,%1,%2,%3}, {%4,%5,%6,%7}, {%8,%9}, {%0,%1,%2,%3};"
        : "+f"(c[0]), "+f"(c[1]), "+f"(c[2]), "+f"(c[3])
        : "r"(a[0]), "r"(a[1]), "r"(a[2]), "r"(a[3]), "r"(b0), "r"(b1));
}

// tf32-round a float4 and scatter into fragment layout: elements e=0..3 go to
// consecutive lanes (stride 16B = 4 floats), same reg slot.
__device__ __forceinline__ void stash4(float* p, float4 v) {
    p[0]  = __uint_as_float(f2tf(v.x));
    p[4]  = __uint_as_float(f2tf(v.y));
    p[8]  = __uint_as_float(f2tf(v.z));
    p[12] = __uint_as_float(f2tf(v.w));
}

// C[m,n] = sum_k A[m,k]*B[n,k];  A:[M,K] f32 row-major, B:[N,K] f32 row-major.
__global__ __launch_bounds__(NTH, 1)
void gemm_tf32_v2(const float* __restrict__ A,
                  const float* __restrict__ B,
                  float* __restrict__ C)
{
    extern __shared__ float sm[];
    const int tid  = threadIdx.x;
    const int wid  = tid >> 5;
    const int lane = tid & 31;
    const int wm   = wid >> 2;        // 0..3 -> 64-row stripe
    const int wn   = wid & 3;         // 0..3 -> 32-col stripe
    const int lr   = lane >> 2;       // groupID
    const int lc   = lane & 3;        // thread-in-group
    const int bm   = blockIdx.y * BM;
    const int bn   = blockIdx.x * BN;

    // ---- loader precompute ----
    // A: 256 rows x 8 float4 = 2048 slots -> 4 per thread
    int sA[4]; const float4* pA4[4];
    #pragma unroll
    for (int i = 0; i < 4; i++) {
        int f = tid + i * NTH;
        int m = f >> 3, q = f & 7;
        int mt = m >> 4, mlr = m & 7, mh = (m >> 3) & 1;
        int ks = q >> 1, kh = q & 1;
        sA[i]  = ks * A_KSB + mt * 128 + mlr * 16 + (mh + 2 * kh);
        pA4[i] = (const float4*)A + (size_t)(bm + m) * (K_TOT / 4) + q;
    }
    // B: 128 rows x 8 float4 = 1024 slots -> 2 per thread
    int sB[2]; const float4* pB4[2];
    #pragma unroll
    for (int i = 0; i < 2; i++) {
        int f = tid + i * NTH;
        int n = f >> 3, q = f & 7;
        int nt = n >> 3, nlr = n & 7;
        int ks = q >> 1, kh = q & 1;
        sB[i]  = ks * B_KSB + (nt >> 1) * 128 + nlr * 16 + (kh + 2 * (nt & 1));
        pB4[i] = (const float4*)B + (size_t)(bn + n) * (K_TOT / 4) + q;
    }

    float acc[4][4][4];
    #pragma unroll
    for (int a = 0; a < 4; a++)
        #pragma unroll
        for (int b = 0; b < 4; b++)
            #pragma unroll
            for (int r = 0; r < 4; r++) acc[a][b][r] = 0.0f;

    // ---- prologue: chunk 0 -> stage 0 ----
    float4 ra[4], rb[2];
    #pragma unroll
    for (int i = 0; i < 4; i++) ra[i] = pA4[i][0];
    #pragma unroll
    for (int i = 0; i < 2; i++) rb[i] = pB4[i][0];
    {
        float* dA = sm;
        float* dB = sm + A_HALF;
        #pragma unroll
        for (int i = 0; i < 4; i++) stash4(dA + sA[i], ra[i]);
        #pragma unroll
        for (int i = 0; i < 2; i++) stash4(dB + sB[i], rb[i]);
    }
    __syncthreads();

    // ---- main loop: one sync per chunk ----
    for (int c = 0; c < NCH; c++) {
        const int st = c & 1;
        if (c + 1 < NCH) {
            #pragma unroll
            for (int i = 0; i < 4; i++) ra[i] = pA4[i][(c + 1) * 8];
            #pragma unroll
            for (int i = 0; i < 2; i++) rb[i] = pB4[i][(c + 1) * 8];
        }

        const float* As = sm + st * STG_FLOATS;
        const float* Bs = As + A_HALF;
        #pragma unroll
        for (int ks = 0; ks < 4; ks++) {
            float4 av[4], bv[2];
            #pragma unroll
            for (int t = 0; t < 4; t++)
                av[t] = *(const float4*)(As + ks * A_KSB + (wm * 4 + t) * 128 + lane * 4);
            #pragma unroll
            for (int p = 0; p < 2; p++)
                bv[p] = *(const float4*)(Bs + ks * B_KSB + (wn * 2 + p) * 128 + lane * 4);
            #pragma unroll
            for (int mt = 0; mt < 4; mt++) {
                const uint32_t* af = (const uint32_t*)&av[mt];
                #pragma unroll
                for (int nt = 0; nt < 4; nt++) {
                    const uint32_t* bw = (const uint32_t*)&bv[nt >> 1];
                    uint32_t b0 = (nt & 1) ? bw[2] : bw[0];
                    uint32_t b1 = (nt & 1) ? bw[3] : bw[1];
                    mma8(acc[mt][nt], af, b0, b1);
                }
            }
        }

        if (c + 1 < NCH) {
            float* dA = sm + ((c + 1) & 1) * STG_FLOATS;
            float* dB = dA + A_HALF;
            #pragma unroll
            for (int i = 0; i < 4; i++) stash4(dA + sA[i], ra[i]);
            #pragma unroll
            for (int i = 0; i < 2; i++) stash4(dB + sB[i], rb[i]);
        }
        __syncthreads();
    }

    // ---- epilogue ----
    #pragma unroll
    for (int mt = 0; mt < 4; mt++) {
        int m = bm + wm * 64 + mt * 16 + lr;
        float* crow = C + (size_t)m * N_TOT + bn + wn * 32;
        #pragma unroll
        for (int nt = 0; nt < 4; nt++) {
            int nf = nt * 8 + lc * 2;
            *(float2*)(crow + nf) = make_float2(acc[mt][nt][0], acc[mt][nt][1]);
            *(float2*)(crow + nf + (size_t)8 * N_TOT) =
                make_float2(acc[mt][nt][2], acc[mt][nt][3]);
        }
    }
}

// ---------------- 5-tap Gaussian window, per-head shift {0,-1,+1,0}x2 ---------
__global__ void conv_kernel(const float4* __restrict__ V, float4* __restrict__ Vc)
{
    int idx = blockIdx.x * blockDim.x + threadIdx.x;   // M_TOT*128 threads
    int c4  = idx & 127;
    int m   = idx >> 7;
    int s   = m & 4095;
    int mb0 = m - s;
    int hm  = (c4 >> 4) & 3;
    int shift = (hm == 1) ? -1 : ((hm == 2) ? 1 : 0);

    const float F[5] = {0.05399096651318806f, 0.24197072451914337f,
                        0.3989422804014327f,  0.24197072451914337f,
                        0.05399096651318806f};

    float ax = 0.f, ay = 0.f, az = 0.f, aw = 0.f;
    #pragma unroll
    for (int j = 0; j < 5; j++) {
        int ss = s + shift + j - 2;
        if (ss >= 0 && ss < 4096) {
            float4 v = V[(size_t)(mb0 + ss) * 128 + c4];
            ax += F[j] * v.x; ay += F[j] * v.y; az += F[j] * v.z; aw += F[j] * v.w;
        }
    }
    Vc[idx] = make_float4(ax, ay, az, aw);
}

// ---------------- launcher ----------------
extern "C" void kernel_launch(void* const* d_in, const int* in_sizes, int n_in,
                              void* d_out, int out_size)
{
    const float* values = (const float*)d_in[0];
    const float* win    = (const float*)d_in[3];
    const float* wout   = (const float*)d_in[4];
    float*       out    = (float*)d_out;

    float *pV = nullptr, *pVc = nullptr;
    cudaGetSymbolAddress((void**)&pV,  g_V);
    cudaGetSymbolAddress((void**)&pVc, g_Vc);

    cudaFuncSetAttribute(gemm_tf32_v2,
                         cudaFuncAttributeMaxDynamicSharedMemorySize, SMEM_BYTES);

    dim3 grid(N_TOT / BN, M_TOT / BM);   // (4, 128)

    gemm_tf32_v2<<<grid, NTH, SMEM_BYTES>>>(values, win, pV);
    conv_kernel<<<(M_TOT * 128) / 256, 256>>>((const float4*)pV, (float4*)pVc);
    gemm_tf32_v2<<<grid, NTH, SMEM_BYTES>>>(pVc, wout, out);
}

// round 6
// speedup vs baseline: 1.6717x; 1.6717x over previous
#include <cuda_runtime.h>
#include <cstdint>

// Shapes (fixed): B=8, S=4096, E=512 -> M=32768, N=K=512
#define M_TOT 32768
#define N_TOT 512
#define K_TOT 512

#define BM 128
#define BN 128
#define BK 32
#define NTH 256
#define NCH (K_TOT / BK)          // 16
#define NSTAGE 3

// smem: per stage A[128][36] + B[128][36] floats (pad 4 keeps 16B align + no conflicts)
#define ROWF 36
#define B_OFF (128 * ROWF)        // floats
#define STG_F (2 * 128 * ROWF)    // 9216 floats / stage
#define SMEM_BYTES (NSTAGE * STG_F * 4)   // 110592 B -> 2 CTAs/SM

// ---------------- scratch (device globals: sanctioned no-alloc path) ----------
__device__ float g_V [(size_t)M_TOT * N_TOT];
__device__ float g_Vc[(size_t)M_TOT * N_TOT];
__device__ float g_Wa[(size_t)N_TOT * K_TOT];   // pre-rounded input_weights
__device__ float g_Wb[(size_t)N_TOT * K_TOT];   // pre-rounded out_proj_w

__device__ __forceinline__ uint32_t f2tf(float x) {
    uint32_t u;
    asm("cvt.rna.tf32.f32 %0, %1;" : "=r"(u) : "f"(x));
    return u;
}
__device__ __forceinline__ uint32_t smem_u32(const void* p) {
    uint32_t a;
    asm("{ .reg .u64 t; cvta.to.shared.u64 t, %1; cvt.u32.u64 %0, t; }" : "=r"(a) : "l"(p));
    return a;
}
__device__ __forceinline__ void cp16(uint32_t saddr, const void* gptr) {
    asm volatile("cp.async.cg.shared.global [%0], [%1], 16;"
                 :: "r"(saddr), "l"(gptr) : "memory");
}
__device__ __forceinline__ void mma8(float* c, const uint32_t* a,
                                     uint32_t b0, uint32_t b1) {
    asm volatile(
        "mma.sync.aligned.m16n8k8.row.col.f32.tf32.tf32.f32 "
        "{%0,%1,%2,%3}, {%4,%5,%6,%7}, {%8,%9}, {%0,%1,%2,%3};"
        : "+f"(c[0]), "+f"(c[1]), "+f"(c[2]), "+f"(c[3])
        : "r"(a[0]), "r"(a[1]), "r"(a[2]), "r"(a[3]), "r"(b0), "r"(b1));
}

// C[m,n] = sum_k A[m,k]*B[n,k]; A:[M,K] f32 row-major, B:[N,K] tf32-prerounded.
// ROUND_A: rna-round A fragments in-loop (false when A is already tf32).
template <bool ROUND_A>
__global__ __launch_bounds__(NTH, 2)
void gemm_cp(const float* __restrict__ A,
             const float* __restrict__ B,
             float* __restrict__ C)
{
    extern __shared__ float sm[];
    const uint32_t sb = smem_u32(sm);
    const int tid  = threadIdx.x;
    const int wid  = tid >> 5;
    const int lane = tid & 31;
    const int wm   = wid >> 2;     // 0..1 -> 64-row stripe
    const int wn   = wid & 3;      // 0..3 -> 32-col stripe
    const int lr   = lane >> 2;
    const int lc   = lane & 3;
    const int bm   = blockIdx.y * BM;
    const int bn   = blockIdx.x * BN;

    const float4* Ag = (const float4*)(A + (size_t)bm * K_TOT);
    const float4* Bg = (const float4*)(B + (size_t)bn * K_TOT);

    // issue one BK-chunk (A tile + B tile) into stage s via cp.async, then commit
    auto issue = [&](int c, int s) {
        const uint32_t sa = sb + (uint32_t)(s * STG_F) * 4u;
        const uint32_t sbB = sa + (uint32_t)B_OFF * 4u;
        #pragma unroll
        for (int i = 0; i < 4; i++) {
            int f = tid + i * NTH, m = f >> 3, q = f & 7;
            cp16(sa + (uint32_t)(m * ROWF + q * 4) * 4u,
                 Ag + (size_t)m * (K_TOT / 4) + c * 8 + q);
        }
        #pragma unroll
        for (int i = 0; i < 4; i++) {
            int f = tid + i * NTH, n = f >> 3, q = f & 7;
            cp16(sbB + (uint32_t)(n * ROWF + q * 4) * 4u,
                 Bg + (size_t)n * (K_TOT / 4) + c * 8 + q);
        }
        asm volatile("cp.async.commit_group;" ::: "memory");
    };

    float acc[4][4][4];
    #pragma unroll
    for (int a = 0; a < 4; a++)
        #pragma unroll
        for (int b = 0; b < 4; b++)
            #pragma unroll
            for (int r = 0; r < 4; r++) acc[a][b][r] = 0.0f;

    issue(0, 0);
    issue(1, 1);

    for (int c = 0; c < NCH; c++) {
        asm volatile("cp.async.wait_group 1;" ::: "memory");
        __syncthreads();                       // stage c ready; all warps past iter c-1
        if (c + 2 < NCH) issue(c + 2, (c + 2) % NSTAGE);
        else asm volatile("cp.async.commit_group;" ::: "memory");  // keep group count

        const float* As = sm + (c % NSTAGE) * STG_F;
        const float* Bs = As + B_OFF;

        #pragma unroll
        for (int ks = 0; ks < 4; ks++) {
            const int kb = ks * 8;
            uint32_t a[4][4], b[4][2];
            #pragma unroll
            for (int mt = 0; mt < 4; mt++) {
                const float* ap = As + (wm * 64 + mt * 16 + lr) * ROWF + kb + lc;
                float a0 = ap[0], a1 = ap[8 * ROWF], a2 = ap[4], a3 = ap[8 * ROWF + 4];
                if (ROUND_A) {
                    a[mt][0] = f2tf(a0); a[mt][1] = f2tf(a1);
                    a[mt][2] = f2tf(a2); a[mt][3] = f2tf(a3);
                } else {
                    a[mt][0] = __float_as_uint(a0); a[mt][1] = __float_as_uint(a1);
                    a[mt][2] = __float_as_uint(a2); a[mt][3] = __float_as_uint(a3);
                }
            }
            #pragma unroll
            for (int nt = 0; nt < 4; nt++) {
                const float* bp = Bs + (wn * 32 + nt * 8 + lr) * ROWF + kb + lc;
                b[nt][0] = __float_as_uint(bp[0]);
                b[nt][1] = __float_as_uint(bp[4]);
            }
            #pragma unroll
            for (int mt = 0; mt < 4; mt++)
                #pragma unroll
                for (int nt = 0; nt < 4; nt++)
                    mma8(acc[mt][nt], a[mt], b[nt][0], b[nt][1]);
        }
    }

    // ---- epilogue ----
    #pragma unroll
    for (int mt = 0; mt < 4; mt++) {
        int m = bm + wm * 64 + mt * 16 + lr;
        float* crow = C + (size_t)m * N_TOT + bn + wn * 32;
        #pragma unroll
        for (int nt = 0; nt < 4; nt++) {
            int nf = nt * 8 + lc * 2;
            *(float2*)(crow + nf) = make_float2(acc[mt][nt][0], acc[mt][nt][1]);
            *(float2*)(crow + nf + (size_t)8 * N_TOT) =
                make_float2(acc[mt][nt][2], acc[mt][nt][3]);
        }
    }
}

// ---------------- weight pre-round to tf32 (rna) ----------------
__global__ void round_w_kernel(const float4* __restrict__ w, float4* __restrict__ o)
{
    int i = blockIdx.x * 256 + threadIdx.x;      // 65536 float4
    float4 v = w[i];
    o[i] = make_float4(__uint_as_float(f2tf(v.x)), __uint_as_float(f2tf(v.y)),
                       __uint_as_float(f2tf(v.z)), __uint_as_float(f2tf(v.w)));
}

// ---- 5-tap Gaussian window, per-head shift {0,-1,+1,0}x2; output tf32-rounded
__global__ void conv_kernel(const float4* __restrict__ V, float4* __restrict__ Vc)
{
    int idx = blockIdx.x * blockDim.x + threadIdx.x;   // M_TOT*128 threads
    int c4  = idx & 127;
    int m   = idx >> 7;
    int s   = m & 4095;
    int mb0 = m - s;
    int hm  = (c4 >> 4) & 3;
    int shift = (hm == 1) ? -1 : ((hm == 2) ? 1 : 0);

    const float F[5] = {0.05399096651318806f, 0.24197072451914337f,
                        0.3989422804014327f,  0.24197072451914337f,
                        0.05399096651318806f};

    float ax = 0.f, ay = 0.f, az = 0.f, aw = 0.f;
    #pragma unroll
    for (int j = 0; j < 5; j++) {
        int ss = s + shift + j - 2;
        if (ss >= 0 && ss < 4096) {
            float4 v = V[(size_t)(mb0 + ss) * 128 + c4];
            ax += F[j] * v.x; ay += F[j] * v.y; az += F[j] * v.z; aw += F[j] * v.w;
        }
    }
    Vc[idx] = make_float4(__uint_as_float(f2tf(ax)), __uint_as_float(f2tf(ay)),
                          __uint_as_float(f2tf(az)), __uint_as_float(f2tf(aw)));
}

// ---------------- launcher ----------------
extern "C" void kernel_launch(void* const* d_in, const int* in_sizes, int n_in,
                              void* d_out, int out_size)
{
    const float* values = (const float*)d_in[0];
    const float* win    = (const float*)d_in[3];
    const float* wout   = (const float*)d_in[4];
    float*       out    = (float*)d_out;

    float *pV, *pVc, *pWa, *pWb;
    cudaGetSymbolAddress((void**)&pV,  g_V);
    cudaGetSymbolAddress((void**)&pVc, g_Vc);
    cudaGetSymbolAddress((void**)&pWa, g_Wa);
    cudaGetSymbolAddress((void**)&pWb, g_Wb);

    cudaFuncSetAttribute(gemm_cp<true>,
                         cudaFuncAttributeMaxDynamicSharedMemorySize, SMEM_BYTES);
    cudaFuncSetAttribute(gemm_cp<false>,
                         cudaFuncAttributeMaxDynamicSharedMemorySize, SMEM_BYTES);

    dim3 grid(N_TOT / BN, M_TOT / BM);   // (4, 256)

    round_w_kernel<<<256, 256>>>((const float4*)win,  (float4*)pWa);
    round_w_kernel<<<256, 256>>>((const float4*)wout, (float4*)pWb);
    gemm_cp<true ><<<grid, NTH, SMEM_BYTES>>>(values, pWa, pV);
    conv_kernel<<<(M_TOT * 128) / 256, 256>>>((const float4*)pV, (float4*)pVc);
    gemm_cp<false><<<grid, NTH, SMEM_BYTES>>>(pVc, pWb, out);
}